// round 7
// baseline (speedup 1.0000x reference)
#include <cuda_runtime.h>

#define BATCH 64
#define TT    200
#define NUM_C 2000
#define DIM   128
#define MM    50
#define MP    56          // M padded; rows 50..55 have w=0 (inert)
#define NX    4000        // distinct x = skill + 2000*answer

// ---------------- scratch (device globals; no allocation allowed) ----------
__device__ __align__(16) float g_w[NUM_C * MP];       // softmax(k·Mk^T) per skill id
__device__ __align__(16) float g_ea[NX * 256];        // [x][0:128]=e, [128:256]=a
__device__ __align__(16) float g_kf[NUM_C * DIM];     // k-part of f GEMM + f_b folded
__device__ __align__(16) float g_reads[BATCH * TT * DIM];
__device__ __align__(16) float g_fWat[DIM * DIM];     // [k][i] = f_W[i*256 + k] (reads part)

__device__ __forceinline__ float sigmoidf_(float x) { return 1.f / (1.f + __expf(-x)); }

// =====================================================================
// w table: softmax(k_emb[c] · Mk^T) over 50 slots; 125 CTAs
// =====================================================================
__global__ void k_wtable(const float* __restrict__ k_emb, const float* __restrict__ Mk) {
    __shared__ float mksh[DIM * 65];   // padded transpose, conflict-free
    __shared__ float ksh[4 * DIM];
    __shared__ float gmax[8], gsum[8];
    int tid = threadIdx.x;
    int c0 = blockIdx.x * 16;
    int m = tid & 63, cg = tid >> 6, wh = (tid >> 5) & 1;
    for (int i = tid; i < MM * DIM; i += 256) {
        int mm = i >> 7, j = i & 127;
        mksh[j * 65 + mm] = Mk[i];
    }
    for (int cl = 0; cl < 16; cl += 4) {
        int c = c0 + cl + cg;
        __syncthreads();
        for (int j = tid; j < 4 * DIM; j += 256)
            ksh[j] = k_emb[(c0 + cl + (j >> 7)) * DIM + (j & 127)];
        __syncthreads();
        float acc = 0.f;
        if (m < MM) {
            #pragma unroll 8
            for (int j = 0; j < DIM; j++) acc = fmaf(ksh[cg * DIM + j], mksh[j * 65 + m], acc);
        }
        float lg = (m < MM) ? acc : -1e30f;
        float mx = lg;
        #pragma unroll
        for (int off = 16; off; off >>= 1) mx = fmaxf(mx, __shfl_xor_sync(~0u, mx, off));
        if ((tid & 31) == 0) gmax[cg * 2 + wh] = mx;
        __syncthreads();
        mx = fmaxf(gmax[cg * 2], gmax[cg * 2 + 1]);
        float ex = (m < MM) ? __expf(lg - mx) : 0.f;
        float sv = ex;
        #pragma unroll
        for (int off = 16; off; off >>= 1) sv += __shfl_xor_sync(~0u, sv, off);
        if ((tid & 31) == 0) gsum[cg * 2 + wh] = sv;
        __syncthreads();
        float s = gsum[cg * 2] + gsum[cg * 2 + 1];
        if (m < MP) g_w[c * MP + m] = ex / s;
    }
}

// =====================================================================
// e/a table: 4000 x 256 GEMM (K=128) + activations; 125 CTAs; plain FMA
// =====================================================================
__global__ void k_ea(const float* __restrict__ v_emb, const float* __restrict__ e_b,
                     const float* __restrict__ a_b,
                     const float* __restrict__ e_W, const float* __restrict__ a_W) {
    __shared__ float Xs[32 * DIM];
    __shared__ __align__(16) float Ws[16 * 260];
    int row0 = blockIdx.x * 32;
    int tid = threadIdx.x;
    int tx = tid & 31, ty = tid >> 5;       // col = tx*8, rows ty*4..+3
    for (int i = tid; i < 32 * DIM; i += 256) Xs[i] = v_emb[row0 * DIM + i];
    float acc[4][8];
    #pragma unroll
    for (int u = 0; u < 4; u++)
        #pragma unroll
        for (int v = 0; v < 8; v++) acc[u][v] = 0.f;
    for (int kc = 0; kc < DIM; kc += 16) {
        __syncthreads();
        for (int i = tid; i < 16 * 256; i += 256) {
            int kk = i & 15, c = i >> 4;    // coalesced read, transposed write
            float v = (c < DIM) ? e_W[c * DIM + kc + kk] : a_W[(c - DIM) * DIM + kc + kk];
            Ws[kk * 260 + c] = v;
        }
        __syncthreads();
        #pragma unroll
        for (int kk = 0; kk < 16; kk++) {
            float xv[4];
            #pragma unroll
            for (int u = 0; u < 4; u++) xv[u] = Xs[(ty * 4 + u) * DIM + kc + kk];
            float4 w0 = *(const float4*)&Ws[kk * 260 + tx * 8];
            float4 w1 = *(const float4*)&Ws[kk * 260 + tx * 8 + 4];
            #pragma unroll
            for (int u = 0; u < 4; u++) {
                acc[u][0] = fmaf(xv[u], w0.x, acc[u][0]);
                acc[u][1] = fmaf(xv[u], w0.y, acc[u][1]);
                acc[u][2] = fmaf(xv[u], w0.z, acc[u][2]);
                acc[u][3] = fmaf(xv[u], w0.w, acc[u][3]);
                acc[u][4] = fmaf(xv[u], w1.x, acc[u][4]);
                acc[u][5] = fmaf(xv[u], w1.y, acc[u][5]);
                acc[u][6] = fmaf(xv[u], w1.z, acc[u][6]);
                acc[u][7] = fmaf(xv[u], w1.w, acc[u][7]);
            }
        }
    }
    int col = tx * 8;
    float barr[8];
    #pragma unroll
    for (int v = 0; v < 8; v++) {
        int cc = col + v;
        barr[v] = (cc < DIM) ? e_b[cc] : a_b[cc - DIM];
    }
    #pragma unroll
    for (int u = 0; u < 4; u++) {
        float o[8];
        #pragma unroll
        for (int v = 0; v < 8; v++) {
            float z = acc[u][v] + barr[v];
            o[v] = (col + v < DIM) ? sigmoidf_(z) : tanhf(z);
        }
        int r = row0 + ty * 4 + u;
        *(float4*)&g_ea[r * 256 + col]     = make_float4(o[0], o[1], o[2], o[3]);
        *(float4*)&g_ea[r * 256 + col + 4] = make_float4(o[4], o[5], o[6], o[7]);
    }
}

// =====================================================================
// kf table (63 CTAs) + f_W(reads-half) transpose (8 CTAs); plain FMA
// =====================================================================
__global__ void k_kfT(const float* __restrict__ k_emb, const float* __restrict__ f_b,
                      const float* __restrict__ f_W) {
    __shared__ float Xs[32 * DIM];
    __shared__ __align__(16) float Ws[16 * 132];
    int bid = blockIdx.x;
    int tid = threadIdx.x;
    if (bid >= 63) {
        int base = (bid - 63) * 2048;
        #pragma unroll
        for (int j = 0; j < 8; j++) {
            int idx = base + j * 256 + tid;
            int k = idx >> 7, ii = idx & 127;
            g_fWat[idx] = f_W[ii * 256 + k];
        }
        return;
    }
    int row0 = bid * 32;
    for (int i = tid; i < 32 * DIM; i += 256) {
        int rr = i >> 7;
        Xs[i] = (row0 + rr < NUM_C) ? k_emb[row0 * DIM + i] : 0.f;
    }
    int tx = tid & 31, ty = tid >> 5;      // col = tx*4
    float acc[4][4];
    #pragma unroll
    for (int u = 0; u < 4; u++)
        #pragma unroll
        for (int v = 0; v < 4; v++) acc[u][v] = 0.f;
    for (int kc = 0; kc < DIM; kc += 16) {
        __syncthreads();
        for (int i = tid; i < 16 * DIM; i += 256) {
            int kk = i & 15, col = i >> 4;
            Ws[kk * 132 + col] = f_W[col * 256 + 128 + kc + kk];
        }
        __syncthreads();
        #pragma unroll
        for (int kk = 0; kk < 16; kk++) {
            float4 w0 = *(const float4*)&Ws[kk * 132 + tx * 4];
            #pragma unroll
            for (int u = 0; u < 4; u++) {
                float x = Xs[(ty * 4 + u) * DIM + kc + kk];
                acc[u][0] = fmaf(x, w0.x, acc[u][0]);
                acc[u][1] = fmaf(x, w0.y, acc[u][1]);
                acc[u][2] = fmaf(x, w0.z, acc[u][2]);
                acc[u][3] = fmaf(x, w0.w, acc[u][3]);
            }
        }
    }
    int col = tx * 4;
    float b0 = f_b[col], b1 = f_b[col + 1], b2 = f_b[col + 2], b3 = f_b[col + 3];
    #pragma unroll
    for (int u = 0; u < 4; u++) {
        int r = row0 + ty * 4 + u;
        if (r < NUM_C)
            *(float4*)&g_kf[r * DIM + col] =
                make_float4(acc[u][0] + b0, acc[u][1] + b1, acc[u][2] + b2, acc[u][3] + b3);
    }
}

// =====================================================================
// Sequential scan: 128 CTAs = 64 batches x 2 d-halves, 256 threads.
// Epoch-4 barriers (ONE __syncthreads per 4 steps), 8-slot smem ring,
// vectorized LDS: w as 3xLDS.128+LDS.64 (group-padded), e/a packed float2.
// Lane map: mg = lane>>3 (m-group of 14), dd = wid*8 + (lane&7).
// =====================================================================
__global__ void k_scan(const int* __restrict__ skill, const int* __restrict__ answer,
                       const float* __restrict__ Mv0) {
    __shared__ int s_sk[TT], s_x[TT];
    __shared__ __align__(16) float  w_sh[8][64];     // [slot][mg*16 + i], i<14
    __shared__ __align__(16) float2 ea_sh[8][64];    // [slot][dd] = (e, a)
    int b = blockIdx.x >> 1;
    int dbase = (blockIdx.x & 1) * 64;
    int tid = threadIdx.x;
    int wid = tid >> 5, lane = tid & 31;
    int mg = lane >> 3, ds = lane & 7;
    int dd = wid * 8 + ds;                 // 0..63 within half

    for (int t = tid; t < TT; t += 256) {
        int s = skill[b * TT + t];
        int aa = answer[b * TT + t];
        if (aa > 1) aa = 1;
        s_sk[t] = s;
        s_x[t] = s + NUM_C * aa;
    }

    float mv[14];
    #pragma unroll
    for (int i = 0; i < 14; i++) {
        int m = mg * 14 + i;
        mv[i] = (m < MM) ? Mv0[m * DIM + dbase + dd] : 0.f;
    }
    __syncthreads();   // s_sk/s_x visible

    // gather roles: tid<56 -> w, 64..127 -> e, 128..191 -> a
    bool isW = tid < MP;
    bool isE = (tid >= 64) && (tid < 128);
    bool isA = (tid >= 128) && (tid < 192);
    bool lp = isW || isE || isA;
    int wdst = isW ? ((tid / 14) * 16 + tid % 14) : 0;   // padded-group dst
    int eoff = isE ? (dbase + (tid - 64)) : (128 + dbase + (tid - 128));

    #define GATHER(ts) (isW ? g_w[s_sk[ts] * MP + tid] : g_ea[s_x[ts] * 256 + eoff])
    #define PUT(sl, v) do { \
        if (isW)      w_sh[sl][wdst] = (v); \
        else if (isE) ea_sh[sl][tid - 64].x = (v); \
        else if (isA) ea_sh[sl][tid - 128].y = (v); \
    } while (0)

    float pfR[4] = {0.f, 0.f, 0.f, 0.f};
    if (lp) {
        float pre[8];
        #pragma unroll
        for (int r = 0; r < 8; r++) pre[r] = GATHER(r);
        #pragma unroll
        for (int r = 0; r < 8; r++) PUT(r, pre[r]);
        #pragma unroll
        for (int j = 0; j < 4; j++) pfR[j] = GATHER(8 + j);
    }
    __syncthreads();

    int outbase = (b * TT) * DIM + dbase + dd;

    for (int t0 = 0; t0 < TT; t0 += 4) {
        // ---- STS: steps t0+4..t0+7 from pfR (loaded last epoch) ----
        if (t0 > 0 && lp) {
            #pragma unroll
            for (int j = 0; j < 4; j++) {
                int ts = t0 + 4 + j;
                if (ts < TT) PUT(ts & 7, pfR[j]);
            }
        }
        // ---- LDG: steps t0+8..t0+11 into pfR ----
        if (lp) {
            #pragma unroll
            for (int j = 0; j < 4; j++) {
                int ts = t0 + 8 + j;
                if (ts < TT) pfR[j] = GATHER(ts);
            }
        }
        // ---- compute steps t0..t0+3 ----
        #pragma unroll
        for (int q = 0; q < 4; q++) {
            int t = t0 + q;
            int sl = t & 7;
            float2 ea = ea_sh[sl][dd];
            float4 w0 = *(const float4*)&w_sh[sl][mg * 16];
            float4 w1 = *(const float4*)&w_sh[sl][mg * 16 + 4];
            float4 w2 = *(const float4*)&w_sh[sl][mg * 16 + 8];
            float2 w3 = *(const float2*)&w_sh[sl][mg * 16 + 12];
            float wv[14] = {w0.x, w0.y, w0.z, w0.w, w1.x, w1.y, w1.z, w1.w,
                            w2.x, w2.y, w2.z, w2.w, w3.x, w3.y};
            float acc = 0.f;
            #pragma unroll
            for (int i = 0; i < 14; i++) {
                acc = fmaf(wv[i], mv[i], acc);                         // PRE-update read
                mv[i] = fmaf(wv[i], fmaf(-ea.x, mv[i], ea.y), mv[i]);
            }
            acc += __shfl_xor_sync(~0u, acc, 8);
            acc += __shfl_xor_sync(~0u, acc, 16);
            if (mg == 0) g_reads[outbase + t * DIM] = acc;
        }
        __syncthreads();
    }
    #undef GATHER
    #undef PUT
}

// =====================================================================
// fpred: f = tanh(reads@fWat + kf[skill]); gathered pred. 199 CTAs x 64.
// =====================================================================
__global__ void k_fpred(const int* __restrict__ skill, const float* __restrict__ p_W,
                        const float* __restrict__ p_b, float* __restrict__ out) {
    __shared__ float Xs[64][130];                 // reads tile; later reused for f
    __shared__ __align__(16) float Ws[16][DIM];
    __shared__ int s_kf[64], s_nx[64], roff[64];
    int row0 = blockIdx.x * 64;
    int tid = threadIdx.x;
    if (tid < 64) {
        int r = row0 + tid;
        int b = r / 199;
        int t = r - b * 199;
        s_kf[tid] = skill[b * TT + t];
        s_nx[tid] = skill[b * TT + t + 1];
        roff[tid] = (b * TT + t) * DIM;
    }
    __syncthreads();
    for (int i = tid; i < 64 * DIM; i += 256) {
        int rr = i >> 7, k = i & 127;
        Xs[rr][k] = g_reads[roff[rr] + k];
    }
    int tx = tid & 15, ty = tid >> 4;   // col = tx*8, rows = ty*4..
    float acc[4][8];
    #pragma unroll
    for (int u = 0; u < 4; u++)
        #pragma unroll
        for (int v = 0; v < 8; v++) acc[u][v] = 0.f;
    for (int kc = 0; kc < DIM; kc += 16) {
        __syncthreads();
        for (int i = tid; i < 16 * DIM; i += 256)
            Ws[i >> 7][i & 127] = g_fWat[(kc + (i >> 7)) * DIM + (i & 127)];
        __syncthreads();
        #pragma unroll
        for (int kk = 0; kk < 16; kk++) {
            float xv[4];
            #pragma unroll
            for (int u = 0; u < 4; u++) xv[u] = Xs[ty * 4 + u][kc + kk];
            float4 w0 = *(const float4*)&Ws[kk][tx * 8];
            float4 w1 = *(const float4*)&Ws[kk][tx * 8 + 4];
            #pragma unroll
            for (int u = 0; u < 4; u++) {
                acc[u][0] = fmaf(xv[u], w0.x, acc[u][0]);
                acc[u][1] = fmaf(xv[u], w0.y, acc[u][1]);
                acc[u][2] = fmaf(xv[u], w0.z, acc[u][2]);
                acc[u][3] = fmaf(xv[u], w0.w, acc[u][3]);
                acc[u][4] = fmaf(xv[u], w1.x, acc[u][4]);
                acc[u][5] = fmaf(xv[u], w1.y, acc[u][5]);
                acc[u][6] = fmaf(xv[u], w1.z, acc[u][6]);
                acc[u][7] = fmaf(xv[u], w1.w, acc[u][7]);
            }
        }
    }
    __syncthreads();   // everyone done reading Xs -> overwrite with f
    int col = tx * 8;
    #pragma unroll
    for (int u = 0; u < 4; u++) {
        int row = ty * 4 + u;
        int sc = s_kf[row];
        float4 k0 = *(const float4*)&g_kf[sc * DIM + col];
        float4 k1 = *(const float4*)&g_kf[sc * DIM + col + 4];
        Xs[row][col + 0] = tanhf(acc[u][0] + k0.x);
        Xs[row][col + 1] = tanhf(acc[u][1] + k0.y);
        Xs[row][col + 2] = tanhf(acc[u][2] + k0.z);
        Xs[row][col + 3] = tanhf(acc[u][3] + k0.w);
        Xs[row][col + 4] = tanhf(acc[u][4] + k1.x);
        Xs[row][col + 5] = tanhf(acc[u][5] + k1.y);
        Xs[row][col + 6] = tanhf(acc[u][6] + k1.z);
        Xs[row][col + 7] = tanhf(acc[u][7] + k1.w);
    }
    __syncthreads();
    int wid = tid >> 5, lane = tid & 31;
    for (int rr = wid * 8; rr < wid * 8 + 8; rr++) {
        int ns = s_nx[rr];
        int idx = (ns < NUM_C) ? ns : (NUM_C - 1);
        const float* pw = p_W + idx * DIM;
        float a = 0.f;
        #pragma unroll
        for (int q = 0; q < 4; q++) a = fmaf(Xs[rr][lane + 32 * q], pw[lane + 32 * q], a);
        #pragma unroll
        for (int off = 16; off; off >>= 1) a += __shfl_xor_sync(~0u, a, off);
        if (lane == 0) {
            float pr = sigmoidf_(a + p_b[idx]);
            out[row0 + rr] = (ns < NUM_C) ? pr : 0.f;
        }
    }
}

// ---------------- launch: forked-capture stream graph ----------------------
extern "C" void kernel_launch(void* const* d_in, const int* in_sizes, int n_in,
                              void* d_out, int out_size) {
    const int*   skill  = (const int*)d_in[0];
    const int*   answer = (const int*)d_in[1];
    const float* k_emb  = (const float*)d_in[2];
    const float* v_emb  = (const float*)d_in[3];
    const float* Mk     = (const float*)d_in[4];
    const float* Mv0    = (const float*)d_in[5];
    const float* f_W    = (const float*)d_in[6];
    const float* f_b    = (const float*)d_in[7];
    const float* p_W    = (const float*)d_in[8];
    const float* p_b    = (const float*)d_in[9];
    const float* e_W    = (const float*)d_in[10];
    const float* e_b    = (const float*)d_in[11];
    const float* a_W    = (const float*)d_in[12];
    const float* a_b    = (const float*)d_in[13];
    float* out = (float*)d_out;

    static cudaStream_t sA = nullptr, sB = nullptr, sC = nullptr;
    static cudaEvent_t evR = nullptr, evA = nullptr, evB = nullptr, evC = nullptr;
    if (!sA) {   // first call = correctness run (not captured): safe to create
        cudaStreamCreateWithFlags(&sA, cudaStreamNonBlocking);
        cudaStreamCreateWithFlags(&sB, cudaStreamNonBlocking);
        cudaStreamCreateWithFlags(&sC, cudaStreamNonBlocking);
        cudaEventCreateWithFlags(&evR, cudaEventDisableTiming);
        cudaEventCreateWithFlags(&evA, cudaEventDisableTiming);
        cudaEventCreateWithFlags(&evB, cudaEventDisableTiming);
        cudaEventCreateWithFlags(&evC, cudaEventDisableTiming);
    }

    cudaEventRecord(evR, 0);
    cudaStreamWaitEvent(sA, evR, 0);
    cudaStreamWaitEvent(sB, evR, 0);
    cudaStreamWaitEvent(sC, evR, 0);

    k_wtable<<<125, 256, 0, sA>>>(k_emb, Mk);
    k_ea    <<<125, 256, 0, sB>>>(v_emb, e_b, a_b, e_W, a_W);
    k_kfT   <<<71, 256, 0, sC>>>(k_emb, f_b, f_W);      // overlaps scan

    cudaEventRecord(evA, sA);
    cudaEventRecord(evB, sB);
    cudaEventRecord(evC, sC);

    cudaStreamWaitEvent(0, evA, 0);
    cudaStreamWaitEvent(0, evB, 0);
    k_scan<<<128, 256>>>(skill, answer, Mv0);

    cudaStreamWaitEvent(0, evC, 0);
    k_fpred<<<199, 256>>>(skill, p_W, p_b, out);
}

// round 8
// speedup vs baseline: 1.0403x; 1.0403x over previous
#include <cuda_runtime.h>

#define BATCH 64
#define TT    200
#define NUM_C 2000
#define DIM   128
#define MM    50
#define MP    56          // M padded; rows 50..55 have w=0 (inert)
#define NX    4000        // distinct x = skill + 2000*answer

// ---------------- scratch (device globals; no allocation allowed) ----------
__device__ __align__(16) float g_w[NUM_C * MP];       // softmax(k·Mk^T) per skill id
__device__ __align__(16) float g_ea[NX * 256];        // [x][0:128]=e, [128:256]=a
__device__ __align__(16) float g_kf[NUM_C * DIM];     // k-part of f GEMM + f_b folded
__device__ __align__(16) float g_reads[BATCH * TT * DIM];
__device__ __align__(16) float g_fWat[DIM * DIM];     // [k][i] = f_W[i*256 + k] (reads part)

__device__ __forceinline__ float sigmoidf_(float x) { return 1.f / (1.f + __expf(-x)); }

// =====================================================================
// w table: softmax(k_emb[c] · Mk^T) over 50 slots; 125 CTAs
// =====================================================================
__global__ void k_wtable(const float* __restrict__ k_emb, const float* __restrict__ Mk) {
    __shared__ float mksh[DIM * 65];   // padded transpose, conflict-free
    __shared__ float ksh[4 * DIM];
    __shared__ float gmax[8], gsum[8];
    int tid = threadIdx.x;
    int c0 = blockIdx.x * 16;
    int m = tid & 63, cg = tid >> 6, wh = (tid >> 5) & 1;
    for (int i = tid; i < MM * DIM; i += 256) {
        int mm = i >> 7, j = i & 127;
        mksh[j * 65 + mm] = Mk[i];
    }
    for (int cl = 0; cl < 16; cl += 4) {
        int c = c0 + cl + cg;
        __syncthreads();
        for (int j = tid; j < 4 * DIM; j += 256)
            ksh[j] = k_emb[(c0 + cl + (j >> 7)) * DIM + (j & 127)];
        __syncthreads();
        float acc = 0.f;
        if (m < MM) {
            #pragma unroll 8
            for (int j = 0; j < DIM; j++) acc = fmaf(ksh[cg * DIM + j], mksh[j * 65 + m], acc);
        }
        float lg = (m < MM) ? acc : -1e30f;
        float mx = lg;
        #pragma unroll
        for (int off = 16; off; off >>= 1) mx = fmaxf(mx, __shfl_xor_sync(~0u, mx, off));
        if ((tid & 31) == 0) gmax[cg * 2 + wh] = mx;
        __syncthreads();
        mx = fmaxf(gmax[cg * 2], gmax[cg * 2 + 1]);
        float ex = (m < MM) ? __expf(lg - mx) : 0.f;
        float sv = ex;
        #pragma unroll
        for (int off = 16; off; off >>= 1) sv += __shfl_xor_sync(~0u, sv, off);
        if ((tid & 31) == 0) gsum[cg * 2 + wh] = sv;
        __syncthreads();
        float s = gsum[cg * 2] + gsum[cg * 2 + 1];
        if (m < MP) g_w[c * MP + m] = ex / s;
    }
}

// =====================================================================
// e/a table: 4000 x 256 GEMM (K=128) + activations; 125 CTAs; plain FMA
// =====================================================================
__global__ void k_ea(const float* __restrict__ v_emb, const float* __restrict__ e_b,
                     const float* __restrict__ a_b,
                     const float* __restrict__ e_W, const float* __restrict__ a_W) {
    __shared__ float Xs[32 * DIM];
    __shared__ __align__(16) float Ws[16 * 260];
    int row0 = blockIdx.x * 32;
    int tid = threadIdx.x;
    int tx = tid & 31, ty = tid >> 5;       // col = tx*8, rows ty*4..+3
    for (int i = tid; i < 32 * DIM; i += 256) Xs[i] = v_emb[row0 * DIM + i];
    float acc[4][8];
    #pragma unroll
    for (int u = 0; u < 4; u++)
        #pragma unroll
        for (int v = 0; v < 8; v++) acc[u][v] = 0.f;
    for (int kc = 0; kc < DIM; kc += 16) {
        __syncthreads();
        for (int i = tid; i < 16 * 256; i += 256) {
            int kk = i & 15, c = i >> 4;    // coalesced read, transposed write
            float v = (c < DIM) ? e_W[c * DIM + kc + kk] : a_W[(c - DIM) * DIM + kc + kk];
            Ws[kk * 260 + c] = v;
        }
        __syncthreads();
        #pragma unroll
        for (int kk = 0; kk < 16; kk++) {
            float xv[4];
            #pragma unroll
            for (int u = 0; u < 4; u++) xv[u] = Xs[(ty * 4 + u) * DIM + kc + kk];
            float4 w0 = *(const float4*)&Ws[kk * 260 + tx * 8];
            float4 w1 = *(const float4*)&Ws[kk * 260 + tx * 8 + 4];
            #pragma unroll
            for (int u = 0; u < 4; u++) {
                acc[u][0] = fmaf(xv[u], w0.x, acc[u][0]);
                acc[u][1] = fmaf(xv[u], w0.y, acc[u][1]);
                acc[u][2] = fmaf(xv[u], w0.z, acc[u][2]);
                acc[u][3] = fmaf(xv[u], w0.w, acc[u][3]);
                acc[u][4] = fmaf(xv[u], w1.x, acc[u][4]);
                acc[u][5] = fmaf(xv[u], w1.y, acc[u][5]);
                acc[u][6] = fmaf(xv[u], w1.z, acc[u][6]);
                acc[u][7] = fmaf(xv[u], w1.w, acc[u][7]);
            }
        }
    }
    int col = tx * 8;
    float barr[8];
    #pragma unroll
    for (int v = 0; v < 8; v++) {
        int cc = col + v;
        barr[v] = (cc < DIM) ? e_b[cc] : a_b[cc - DIM];
    }
    #pragma unroll
    for (int u = 0; u < 4; u++) {
        float o[8];
        #pragma unroll
        for (int v = 0; v < 8; v++) {
            float z = acc[u][v] + barr[v];
            o[v] = (col + v < DIM) ? sigmoidf_(z) : tanhf(z);
        }
        int r = row0 + ty * 4 + u;
        *(float4*)&g_ea[r * 256 + col]     = make_float4(o[0], o[1], o[2], o[3]);
        *(float4*)&g_ea[r * 256 + col + 4] = make_float4(o[4], o[5], o[6], o[7]);
    }
}

// =====================================================================
// kf table (63 CTAs) + f_W(reads-half) transpose (8 CTAs); plain FMA
// =====================================================================
__global__ void k_kfT(const float* __restrict__ k_emb, const float* __restrict__ f_b,
                      const float* __restrict__ f_W) {
    __shared__ float Xs[32 * DIM];
    __shared__ __align__(16) float Ws[16 * 132];
    int bid = blockIdx.x;
    int tid = threadIdx.x;
    if (bid >= 63) {
        int base = (bid - 63) * 2048;
        #pragma unroll
        for (int j = 0; j < 8; j++) {
            int idx = base + j * 256 + tid;
            int k = idx >> 7, ii = idx & 127;
            g_fWat[idx] = f_W[ii * 256 + k];
        }
        return;
    }
    int row0 = bid * 32;
    for (int i = tid; i < 32 * DIM; i += 256) {
        int rr = i >> 7;
        Xs[i] = (row0 + rr < NUM_C) ? k_emb[row0 * DIM + i] : 0.f;
    }
    int tx = tid & 31, ty = tid >> 5;      // col = tx*4
    float acc[4][4];
    #pragma unroll
    for (int u = 0; u < 4; u++)
        #pragma unroll
        for (int v = 0; v < 4; v++) acc[u][v] = 0.f;
    for (int kc = 0; kc < DIM; kc += 16) {
        __syncthreads();
        for (int i = tid; i < 16 * DIM; i += 256) {
            int kk = i & 15, col = i >> 4;
            Ws[kk * 132 + col] = f_W[col * 256 + 128 + kc + kk];
        }
        __syncthreads();
        #pragma unroll
        for (int kk = 0; kk < 16; kk++) {
            float4 w0 = *(const float4*)&Ws[kk * 132 + tx * 4];
            #pragma unroll
            for (int u = 0; u < 4; u++) {
                float x = Xs[(ty * 4 + u) * DIM + kc + kk];
                acc[u][0] = fmaf(x, w0.x, acc[u][0]);
                acc[u][1] = fmaf(x, w0.y, acc[u][1]);
                acc[u][2] = fmaf(x, w0.z, acc[u][2]);
                acc[u][3] = fmaf(x, w0.w, acc[u][3]);
            }
        }
    }
    int col = tx * 4;
    float b0 = f_b[col], b1 = f_b[col + 1], b2 = f_b[col + 2], b3 = f_b[col + 3];
    #pragma unroll
    for (int u = 0; u < 4; u++) {
        int r = row0 + ty * 4 + u;
        if (r < NUM_C)
            *(float4*)&g_kf[r * DIM + col] =
                make_float4(acc[u][0] + b0, acc[u][1] + b1, acc[u][2] + b2, acc[u][3] + b3);
    }
}

// =====================================================================
// Sequential scan: 128 CTAs = 64 batches x 2 d-halves, **512 threads**.
// R6-proven structure: ONE sync/step, depth-4 compile-time rotation,
// scalar broadcast LDS. New map: thread owns 7 m x 1 d.
//   lane = mg*4 + dq  (mg = lane>>2 in 0..7, dq = lane&3)
//   dd   = wid*4 + dq (16 warps x 4 = 64 d)
// Reduction over 8 m-groups = 3 in-warp shfl_xor (4, 8, 16).
// 4 warps/SMSP (was 2) -> double the independent chains per scheduler.
// =====================================================================
__global__ __launch_bounds__(512) void k_scan(const int* __restrict__ skill,
                                              const int* __restrict__ answer,
                                              const float* __restrict__ Mv0) {
    __shared__ int s_sk[TT], s_x[TT];
    __shared__ __align__(16) float w_sh[4][MP];
    __shared__ __align__(16) float e_sh[4][64];
    __shared__ __align__(16) float a_sh[4][64];
    int b = blockIdx.x >> 1;
    int dbase = (blockIdx.x & 1) * 64;
    int tid = threadIdx.x;
    int wid = tid >> 5, lane = tid & 31;
    int mg = lane >> 2, dq = lane & 3;
    int dd = wid * 4 + dq;                 // 0..63 within half

    for (int t = tid; t < TT; t += 512) {
        int s = skill[b * TT + t];
        int aa = answer[b * TT + t];
        if (aa > 1) aa = 1;
        s_sk[t] = s;
        s_x[t] = s + NUM_C * aa;
    }

    float mv[7];
    #pragma unroll
    for (int i = 0; i < 7; i++) {
        int m = mg * 7 + i;
        mv[i] = (m < MM) ? Mv0[m * DIM + dbase + dd] : 0.f;
    }
    __syncthreads();   // s_sk/s_x visible

    bool lp = tid < 184;   // gather roles: <56 w, <120 e, <184 a
    float pfR[4];          // pfR[s&3] holds gathered value for step s
    pfR[0] = 0.f; pfR[1] = 0.f; pfR[2] = 0.f; pfR[3] = 0.f;
    if (lp) {
        float v0;
        if (tid < MP) {
            v0      = g_w[s_sk[0] * MP + tid];
            pfR[1]  = g_w[s_sk[1] * MP + tid];
            pfR[2]  = g_w[s_sk[2] * MP + tid];
            pfR[3]  = g_w[s_sk[3] * MP + tid];
            w_sh[0][tid] = v0;
        } else if (tid < 120) {
            int o = dbase + (tid - 56);
            v0      = g_ea[s_x[0] * 256 + o];
            pfR[1]  = g_ea[s_x[1] * 256 + o];
            pfR[2]  = g_ea[s_x[2] * 256 + o];
            pfR[3]  = g_ea[s_x[3] * 256 + o];
            e_sh[0][tid - 56] = v0;
        } else {
            int o = 128 + dbase + (tid - 120);
            v0      = g_ea[s_x[0] * 256 + o];
            pfR[1]  = g_ea[s_x[1] * 256 + o];
            pfR[2]  = g_ea[s_x[2] * 256 + o];
            pfR[3]  = g_ea[s_x[3] * 256 + o];
            a_sh[0][tid - 120] = v0;
        }
    }
    __syncthreads();

    int outbase = (b * TT) * DIM + dbase + dd;

    for (int t0 = 0; t0 < TT; t0 += 4) {
        #pragma unroll
        for (int q = 0; q < 4; q++) {
            int t = t0 + q;
            // ---- compute step t from buffers[q] ----
            float e = e_sh[q][dd];
            float a = a_sh[q][dd];
            float acc = 0.f;
            #pragma unroll
            for (int i = 0; i < 7; i++) {
                float wm = w_sh[q][mg * 7 + i];
                acc = fmaf(wm, mv[i], acc);                      // PRE-update read
                mv[i] = fmaf(wm, fmaf(-e, mv[i], a), mv[i]);
            }
            acc += __shfl_xor_sync(~0u, acc, 4);
            acc += __shfl_xor_sync(~0u, acc, 8);
            acc += __shfl_xor_sync(~0u, acc, 16);
            if (mg == 0) g_reads[outbase + t * DIM] = acc;
            // ---- STS buffers for step t+1 (value loaded at t-3) ----
            if (lp && t + 1 < TT) {
                float pv = pfR[(q + 1) & 3];
                if (tid < MP)       w_sh[(q + 1) & 3][tid] = pv;
                else if (tid < 120) e_sh[(q + 1) & 3][tid - 56] = pv;
                else                a_sh[(q + 1) & 3][tid - 120] = pv;
            }
            // ---- LDG gather for step t+4 into just-freed slot q ----
            if (lp && t + 4 < TT) {
                float nv;
                if (tid < MP)       nv = g_w[s_sk[t + 4] * MP + tid];
                else if (tid < 120) nv = g_ea[s_x[t + 4] * 256 + dbase + (tid - 56)];
                else                nv = g_ea[s_x[t + 4] * 256 + 128 + dbase + (tid - 120)];
                pfR[q] = nv;
            }
            __syncthreads();
        }
    }
}

// =====================================================================
// fpred: f = tanh(reads@fWat + kf[skill]); gathered pred. 199 CTAs x 64.
// =====================================================================
__global__ void k_fpred(const int* __restrict__ skill, const float* __restrict__ p_W,
                        const float* __restrict__ p_b, float* __restrict__ out) {
    __shared__ float Xs[64][130];                 // reads tile; later reused for f
    __shared__ __align__(16) float Ws[16][DIM];
    __shared__ int s_kf[64], s_nx[64], roff[64];
    int row0 = blockIdx.x * 64;
    int tid = threadIdx.x;
    if (tid < 64) {
        int r = row0 + tid;
        int b = r / 199;
        int t = r - b * 199;
        s_kf[tid] = skill[b * TT + t];
        s_nx[tid] = skill[b * TT + t + 1];
        roff[tid] = (b * TT + t) * DIM;
    }
    __syncthreads();
    for (int i = tid; i < 64 * DIM; i += 256) {
        int rr = i >> 7, k = i & 127;
        Xs[rr][k] = g_reads[roff[rr] + k];
    }
    int tx = tid & 15, ty = tid >> 4;   // col = tx*8, rows = ty*4..
    float acc[4][8];
    #pragma unroll
    for (int u = 0; u < 4; u++)
        #pragma unroll
        for (int v = 0; v < 8; v++) acc[u][v] = 0.f;
    for (int kc = 0; kc < DIM; kc += 16) {
        __syncthreads();
        for (int i = tid; i < 16 * DIM; i += 256)
            Ws[i >> 7][i & 127] = g_fWat[(kc + (i >> 7)) * DIM + (i & 127)];
        __syncthreads();
        #pragma unroll
        for (int kk = 0; kk < 16; kk++) {
            float xv[4];
            #pragma unroll
            for (int u = 0; u < 4; u++) xv[u] = Xs[ty * 4 + u][kc + kk];
            float4 w0 = *(const float4*)&Ws[kk][tx * 8];
            float4 w1 = *(const float4*)&Ws[kk][tx * 8 + 4];
            #pragma unroll
            for (int u = 0; u < 4; u++) {
                acc[u][0] = fmaf(xv[u], w0.x, acc[u][0]);
                acc[u][1] = fmaf(xv[u], w0.y, acc[u][1]);
                acc[u][2] = fmaf(xv[u], w0.z, acc[u][2]);
                acc[u][3] = fmaf(xv[u], w0.w, acc[u][3]);
                acc[u][4] = fmaf(xv[u], w1.x, acc[u][4]);
                acc[u][5] = fmaf(xv[u], w1.y, acc[u][5]);
                acc[u][6] = fmaf(xv[u], w1.z, acc[u][6]);
                acc[u][7] = fmaf(xv[u], w1.w, acc[u][7]);
            }
        }
    }
    __syncthreads();   // everyone done reading Xs -> overwrite with f
    int col = tx * 8;
    #pragma unroll
    for (int u = 0; u < 4; u++) {
        int row = ty * 4 + u;
        int sc = s_kf[row];
        float4 k0 = *(const float4*)&g_kf[sc * DIM + col];
        float4 k1 = *(const float4*)&g_kf[sc * DIM + col + 4];
        Xs[row][col + 0] = tanhf(acc[u][0] + k0.x);
        Xs[row][col + 1] = tanhf(acc[u][1] + k0.y);
        Xs[row][col + 2] = tanhf(acc[u][2] + k0.z);
        Xs[row][col + 3] = tanhf(acc[u][3] + k0.w);
        Xs[row][col + 4] = tanhf(acc[u][4] + k1.x);
        Xs[row][col + 5] = tanhf(acc[u][5] + k1.y);
        Xs[row][col + 6] = tanhf(acc[u][6] + k1.z);
        Xs[row][col + 7] = tanhf(acc[u][7] + k1.w);
    }
    __syncthreads();
    int wid = tid >> 5, lane = tid & 31;
    for (int rr = wid * 8; rr < wid * 8 + 8; rr++) {
        int ns = s_nx[rr];
        int idx = (ns < NUM_C) ? ns : (NUM_C - 1);
        const float* pw = p_W + idx * DIM;
        float a = 0.f;
        #pragma unroll
        for (int q = 0; q < 4; q++) a = fmaf(Xs[rr][lane + 32 * q], pw[lane + 32 * q], a);
        #pragma unroll
        for (int off = 16; off; off >>= 1) a += __shfl_xor_sync(~0u, a, off);
        if (lane == 0) {
            float pr = sigmoidf_(a + p_b[idx]);
            out[row0 + rr] = (ns < NUM_C) ? pr : 0.f;
        }
    }
}

// ---------------- launch: forked-capture stream graph ----------------------
extern "C" void kernel_launch(void* const* d_in, const int* in_sizes, int n_in,
                              void* d_out, int out_size) {
    const int*   skill  = (const int*)d_in[0];
    const int*   answer = (const int*)d_in[1];
    const float* k_emb  = (const float*)d_in[2];
    const float* v_emb  = (const float*)d_in[3];
    const float* Mk     = (const float*)d_in[4];
    const float* Mv0    = (const float*)d_in[5];
    const float* f_W    = (const float*)d_in[6];
    const float* f_b    = (const float*)d_in[7];
    const float* p_W    = (const float*)d_in[8];
    const float* p_b    = (const float*)d_in[9];
    const float* e_W    = (const float*)d_in[10];
    const float* e_b    = (const float*)d_in[11];
    const float* a_W    = (const float*)d_in[12];
    const float* a_b    = (const float*)d_in[13];
    float* out = (float*)d_out;

    static cudaStream_t sA = nullptr, sB = nullptr, sC = nullptr;
    static cudaEvent_t evR = nullptr, evA = nullptr, evB = nullptr, evC = nullptr;
    if (!sA) {   // first call = correctness run (not captured): safe to create
        cudaStreamCreateWithFlags(&sA, cudaStreamNonBlocking);
        cudaStreamCreateWithFlags(&sB, cudaStreamNonBlocking);
        cudaStreamCreateWithFlags(&sC, cudaStreamNonBlocking);
        cudaEventCreateWithFlags(&evR, cudaEventDisableTiming);
        cudaEventCreateWithFlags(&evA, cudaEventDisableTiming);
        cudaEventCreateWithFlags(&evB, cudaEventDisableTiming);
        cudaEventCreateWithFlags(&evC, cudaEventDisableTiming);
    }

    cudaEventRecord(evR, 0);
    cudaStreamWaitEvent(sA, evR, 0);
    cudaStreamWaitEvent(sB, evR, 0);
    cudaStreamWaitEvent(sC, evR, 0);

    k_wtable<<<125, 256, 0, sA>>>(k_emb, Mk);
    k_ea    <<<125, 256, 0, sB>>>(v_emb, e_b, a_b, e_W, a_W);
    k_kfT   <<<71, 256, 0, sC>>>(k_emb, f_b, f_W);      // overlaps scan

    cudaEventRecord(evA, sA);
    cudaEventRecord(evB, sB);
    cudaEventRecord(evC, sC);

    cudaStreamWaitEvent(0, evA, 0);
    cudaStreamWaitEvent(0, evB, 0);
    k_scan<<<128, 512>>>(skill, answer, Mv0);

    cudaStreamWaitEvent(0, evC, 0);
    k_fpred<<<199, 256>>>(skill, p_W, p_b, out);
}

// round 9
// speedup vs baseline: 1.1383x; 1.0942x over previous
#include <cuda_runtime.h>

#define BATCH 64
#define TT    200
#define NUM_C 2000
#define DIM   128
#define MM    50
#define MP    56          // M padded; rows 50..55 have w=0 (inert)
#define NX    4000        // distinct x = skill + 2000*answer

// ---------------- scratch (device globals; no allocation allowed) ----------
__device__ __align__(16) float g_w[NUM_C * MP];       // softmax(k·Mk^T) per skill id
__device__ __align__(16) float g_ea[NX * 256];        // [x][0:128]=e, [128:256]=a
__device__ __align__(16) float g_kf[NUM_C * DIM];     // k-part of f GEMM + f_b folded
__device__ __align__(16) float g_reads[BATCH * TT * DIM];
__device__ __align__(16) float g_fWat[DIM * DIM];     // [k][i] = f_W[i*256 + k] (reads part)

__device__ __forceinline__ float sigmoidf_(float x) { return 1.f / (1.f + __expf(-x)); }

// =====================================================================
// w table: softmax(k_emb[c] · Mk^T) over 50 slots; 125 CTAs
// =====================================================================
__global__ void k_wtable(const float* __restrict__ k_emb, const float* __restrict__ Mk) {
    __shared__ float mksh[DIM * 65];   // padded transpose, conflict-free
    __shared__ float ksh[4 * DIM];
    __shared__ float gmax[8], gsum[8];
    int tid = threadIdx.x;
    int c0 = blockIdx.x * 16;
    int m = tid & 63, cg = tid >> 6, wh = (tid >> 5) & 1;
    for (int i = tid; i < MM * DIM; i += 256) {
        int mm = i >> 7, j = i & 127;
        mksh[j * 65 + mm] = Mk[i];
    }
    for (int cl = 0; cl < 16; cl += 4) {
        int c = c0 + cl + cg;
        __syncthreads();
        for (int j = tid; j < 4 * DIM; j += 256)
            ksh[j] = k_emb[(c0 + cl + (j >> 7)) * DIM + (j & 127)];
        __syncthreads();
        float acc = 0.f;
        if (m < MM) {
            #pragma unroll 8
            for (int j = 0; j < DIM; j++) acc = fmaf(ksh[cg * DIM + j], mksh[j * 65 + m], acc);
        }
        float lg = (m < MM) ? acc : -1e30f;
        float mx = lg;
        #pragma unroll
        for (int off = 16; off; off >>= 1) mx = fmaxf(mx, __shfl_xor_sync(~0u, mx, off));
        if ((tid & 31) == 0) gmax[cg * 2 + wh] = mx;
        __syncthreads();
        mx = fmaxf(gmax[cg * 2], gmax[cg * 2 + 1]);
        float ex = (m < MM) ? __expf(lg - mx) : 0.f;
        float sv = ex;
        #pragma unroll
        for (int off = 16; off; off >>= 1) sv += __shfl_xor_sync(~0u, sv, off);
        if ((tid & 31) == 0) gsum[cg * 2 + wh] = sv;
        __syncthreads();
        float s = gsum[cg * 2] + gsum[cg * 2 + 1];
        if (m < MP) g_w[c * MP + m] = ex / s;
    }
}

// =====================================================================
// e/a table: 4000 x 256 GEMM (K=128) + activations; 125 CTAs; plain FMA
// =====================================================================
__global__ void k_ea(const float* __restrict__ v_emb, const float* __restrict__ e_b,
                     const float* __restrict__ a_b,
                     const float* __restrict__ e_W, const float* __restrict__ a_W) {
    __shared__ float Xs[32 * DIM];
    __shared__ __align__(16) float Ws[16 * 260];
    int row0 = blockIdx.x * 32;
    int tid = threadIdx.x;
    int tx = tid & 31, ty = tid >> 5;       // col = tx*8, rows ty*4..+3
    for (int i = tid; i < 32 * DIM; i += 256) Xs[i] = v_emb[row0 * DIM + i];
    float acc[4][8];
    #pragma unroll
    for (int u = 0; u < 4; u++)
        #pragma unroll
        for (int v = 0; v < 8; v++) acc[u][v] = 0.f;
    for (int kc = 0; kc < DIM; kc += 16) {
        __syncthreads();
        for (int i = tid; i < 16 * 256; i += 256) {
            int kk = i & 15, c = i >> 4;    // coalesced read, transposed write
            float v = (c < DIM) ? e_W[c * DIM + kc + kk] : a_W[(c - DIM) * DIM + kc + kk];
            Ws[kk * 260 + c] = v;
        }
        __syncthreads();
        #pragma unroll
        for (int kk = 0; kk < 16; kk++) {
            float xv[4];
            #pragma unroll
            for (int u = 0; u < 4; u++) xv[u] = Xs[(ty * 4 + u) * DIM + kc + kk];
            float4 w0 = *(const float4*)&Ws[kk * 260 + tx * 8];
            float4 w1 = *(const float4*)&Ws[kk * 260 + tx * 8 + 4];
            #pragma unroll
            for (int u = 0; u < 4; u++) {
                acc[u][0] = fmaf(xv[u], w0.x, acc[u][0]);
                acc[u][1] = fmaf(xv[u], w0.y, acc[u][1]);
                acc[u][2] = fmaf(xv[u], w0.z, acc[u][2]);
                acc[u][3] = fmaf(xv[u], w0.w, acc[u][3]);
                acc[u][4] = fmaf(xv[u], w1.x, acc[u][4]);
                acc[u][5] = fmaf(xv[u], w1.y, acc[u][5]);
                acc[u][6] = fmaf(xv[u], w1.z, acc[u][6]);
                acc[u][7] = fmaf(xv[u], w1.w, acc[u][7]);
            }
        }
    }
    int col = tx * 8;
    float barr[8];
    #pragma unroll
    for (int v = 0; v < 8; v++) {
        int cc = col + v;
        barr[v] = (cc < DIM) ? e_b[cc] : a_b[cc - DIM];
    }
    #pragma unroll
    for (int u = 0; u < 4; u++) {
        float o[8];
        #pragma unroll
        for (int v = 0; v < 8; v++) {
            float z = acc[u][v] + barr[v];
            o[v] = (col + v < DIM) ? sigmoidf_(z) : tanhf(z);
        }
        int r = row0 + ty * 4 + u;
        *(float4*)&g_ea[r * 256 + col]     = make_float4(o[0], o[1], o[2], o[3]);
        *(float4*)&g_ea[r * 256 + col + 4] = make_float4(o[4], o[5], o[6], o[7]);
    }
}

// =====================================================================
// kf table (63 CTAs) + f_W(reads-half) transpose (8 CTAs); plain FMA
// =====================================================================
__global__ void k_kfT(const float* __restrict__ k_emb, const float* __restrict__ f_b,
                      const float* __restrict__ f_W) {
    __shared__ float Xs[32 * DIM];
    __shared__ __align__(16) float Ws[16 * 132];
    int bid = blockIdx.x;
    int tid = threadIdx.x;
    if (bid >= 63) {
        int base = (bid - 63) * 2048;
        #pragma unroll
        for (int j = 0; j < 8; j++) {
            int idx = base + j * 256 + tid;
            int k = idx >> 7, ii = idx & 127;
            g_fWat[idx] = f_W[ii * 256 + k];
        }
        return;
    }
    int row0 = bid * 32;
    for (int i = tid; i < 32 * DIM; i += 256) {
        int rr = i >> 7;
        Xs[i] = (row0 + rr < NUM_C) ? k_emb[row0 * DIM + i] : 0.f;
    }
    int tx = tid & 31, ty = tid >> 5;      // col = tx*4
    float acc[4][4];
    #pragma unroll
    for (int u = 0; u < 4; u++)
        #pragma unroll
        for (int v = 0; v < 4; v++) acc[u][v] = 0.f;
    for (int kc = 0; kc < DIM; kc += 16) {
        __syncthreads();
        for (int i = tid; i < 16 * DIM; i += 256) {
            int kk = i & 15, col = i >> 4;
            Ws[kk * 132 + col] = f_W[col * 256 + 128 + kc + kk];
        }
        __syncthreads();
        #pragma unroll
        for (int kk = 0; kk < 16; kk++) {
            float4 w0 = *(const float4*)&Ws[kk * 132 + tx * 4];
            #pragma unroll
            for (int u = 0; u < 4; u++) {
                float x = Xs[(ty * 4 + u) * DIM + kc + kk];
                acc[u][0] = fmaf(x, w0.x, acc[u][0]);
                acc[u][1] = fmaf(x, w0.y, acc[u][1]);
                acc[u][2] = fmaf(x, w0.z, acc[u][2]);
                acc[u][3] = fmaf(x, w0.w, acc[u][3]);
            }
        }
    }
    int col = tx * 4;
    float b0 = f_b[col], b1 = f_b[col + 1], b2 = f_b[col + 2], b3 = f_b[col + 3];
    #pragma unroll
    for (int u = 0; u < 4; u++) {
        int r = row0 + ty * 4 + u;
        if (r < NUM_C)
            *(float4*)&g_kf[r * DIM + col] =
                make_float4(acc[u][0] + b0, acc[u][1] + b1, acc[u][2] + b2, acc[u][3] + b3);
    }
}

// =====================================================================
// Sequential scan: **512 CTAs = 64 b x 8 d-slices of 16**, 128 threads.
// Same per-step math as R8 (7m x 1d per thread, 3-shfl reduce, 1 sync/step,
// depth-4 compile-time rotation) but ~3.5 co-resident CTAs/SM so the
// ~600-cyc per-step latency chain overlaps across 3-4 independent CTAs.
//   lane = mg*4 + dq  (mg = lane>>2 in 0..7, dq = lane&3)
//   dd   = wid*4 + dq (4 warps x 4 = 16 d per CTA)
// =====================================================================
__global__ __launch_bounds__(128) void k_scan(const int* __restrict__ skill,
                                              const int* __restrict__ answer,
                                              const float* __restrict__ Mv0) {
    __shared__ int s_sk[TT], s_x[TT];
    __shared__ __align__(16) float w_sh[4][MP];
    __shared__ __align__(16) float e_sh[4][16];
    __shared__ __align__(16) float a_sh[4][16];
    int b = blockIdx.x >> 3;
    int dbase = (blockIdx.x & 7) * 16;
    int tid = threadIdx.x;
    int wid = tid >> 5, lane = tid & 31;
    int mg = lane >> 2, dq = lane & 3;
    int dd = wid * 4 + dq;                 // 0..15 within slice

    for (int t = tid; t < TT; t += 128) {
        int s = skill[b * TT + t];
        int aa = answer[b * TT + t];
        if (aa > 1) aa = 1;
        s_sk[t] = s;
        s_x[t] = s + NUM_C * aa;
    }

    float mv[7];
    #pragma unroll
    for (int i = 0; i < 7; i++) {
        int m = mg * 7 + i;
        mv[i] = (m < MM) ? Mv0[m * DIM + dbase + dd] : 0.f;
    }
    __syncthreads();   // s_sk/s_x visible

    // gather roles: tid<56 -> w, [64,80) -> e, [80,96) -> a
    bool isW = tid < MP;
    bool isE = (tid >= 64) && (tid < 80);
    bool isA = (tid >= 80) && (tid < 96);
    bool lp = isW || isE || isA;
    int eoff = isE ? (dbase + (tid - 64)) : (128 + dbase + (tid - 80));

    float pfR[4];          // pfR[s&3] holds gathered value for step s
    pfR[0] = 0.f; pfR[1] = 0.f; pfR[2] = 0.f; pfR[3] = 0.f;
    if (lp) {
        float v0;
        if (isW) {
            v0      = g_w[s_sk[0] * MP + tid];
            pfR[1]  = g_w[s_sk[1] * MP + tid];
            pfR[2]  = g_w[s_sk[2] * MP + tid];
            pfR[3]  = g_w[s_sk[3] * MP + tid];
            w_sh[0][tid] = v0;
        } else {
            v0      = g_ea[s_x[0] * 256 + eoff];
            pfR[1]  = g_ea[s_x[1] * 256 + eoff];
            pfR[2]  = g_ea[s_x[2] * 256 + eoff];
            pfR[3]  = g_ea[s_x[3] * 256 + eoff];
            if (isE) e_sh[0][tid - 64] = v0;
            else     a_sh[0][tid - 80] = v0;
        }
    }
    __syncthreads();

    int outbase = (b * TT) * DIM + dbase + dd;

    for (int t0 = 0; t0 < TT; t0 += 4) {
        #pragma unroll
        for (int q = 0; q < 4; q++) {
            int t = t0 + q;
            // ---- compute step t from buffers[q] ----
            float e = e_sh[q][dd];
            float a = a_sh[q][dd];
            float acc = 0.f;
            #pragma unroll
            for (int i = 0; i < 7; i++) {
                float wm = w_sh[q][mg * 7 + i];
                acc = fmaf(wm, mv[i], acc);                      // PRE-update read
                mv[i] = fmaf(wm, fmaf(-e, mv[i], a), mv[i]);
            }
            acc += __shfl_xor_sync(~0u, acc, 4);
            acc += __shfl_xor_sync(~0u, acc, 8);
            acc += __shfl_xor_sync(~0u, acc, 16);
            if (mg == 0) g_reads[outbase + t * DIM] = acc;
            // ---- STS buffers for step t+1 (value loaded at t-3) ----
            if (lp && t + 1 < TT) {
                float pv = pfR[(q + 1) & 3];
                int nb = (q + 1) & 3;
                if (isW)      w_sh[nb][tid] = pv;
                else if (isE) e_sh[nb][tid - 64] = pv;
                else          a_sh[nb][tid - 80] = pv;
            }
            // ---- LDG gather for step t+4 into just-freed slot q ----
            if (lp && t + 4 < TT) {
                float nv;
                if (isW) nv = g_w[s_sk[t + 4] * MP + tid];
                else     nv = g_ea[s_x[t + 4] * 256 + eoff];
                pfR[q] = nv;
            }
            __syncthreads();
        }
    }
}

// =====================================================================
// fpred: f = tanh(reads@fWat + kf[skill]); gathered pred. 199 CTAs x 64.
// =====================================================================
__global__ void k_fpred(const int* __restrict__ skill, const float* __restrict__ p_W,
                        const float* __restrict__ p_b, float* __restrict__ out) {
    __shared__ float Xs[64][130];                 // reads tile; later reused for f
    __shared__ __align__(16) float Ws[16][DIM];
    __shared__ int s_kf[64], s_nx[64], roff[64];
    int row0 = blockIdx.x * 64;
    int tid = threadIdx.x;
    if (tid < 64) {
        int r = row0 + tid;
        int b = r / 199;
        int t = r - b * 199;
        s_kf[tid] = skill[b * TT + t];
        s_nx[tid] = skill[b * TT + t + 1];
        roff[tid] = (b * TT + t) * DIM;
    }
    __syncthreads();
    for (int i = tid; i < 64 * DIM; i += 256) {
        int rr = i >> 7, k = i & 127;
        Xs[rr][k] = g_reads[roff[rr] + k];
    }
    int tx = tid & 15, ty = tid >> 4;   // col = tx*8, rows = ty*4..
    float acc[4][8];
    #pragma unroll
    for (int u = 0; u < 4; u++)
        #pragma unroll
        for (int v = 0; v < 8; v++) acc[u][v] = 0.f;
    for (int kc = 0; kc < DIM; kc += 16) {
        __syncthreads();
        for (int i = tid; i < 16 * DIM; i += 256)
            Ws[i >> 7][i & 127] = g_fWat[(kc + (i >> 7)) * DIM + (i & 127)];
        __syncthreads();
        #pragma unroll
        for (int kk = 0; kk < 16; kk++) {
            float xv[4];
            #pragma unroll
            for (int u = 0; u < 4; u++) xv[u] = Xs[ty * 4 + u][kc + kk];
            float4 w0 = *(const float4*)&Ws[kk][tx * 8];
            float4 w1 = *(const float4*)&Ws[kk][tx * 8 + 4];
            #pragma unroll
            for (int u = 0; u < 4; u++) {
                acc[u][0] = fmaf(xv[u], w0.x, acc[u][0]);
                acc[u][1] = fmaf(xv[u], w0.y, acc[u][1]);
                acc[u][2] = fmaf(xv[u], w0.z, acc[u][2]);
                acc[u][3] = fmaf(xv[u], w0.w, acc[u][3]);
                acc[u][4] = fmaf(xv[u], w1.x, acc[u][4]);
                acc[u][5] = fmaf(xv[u], w1.y, acc[u][5]);
                acc[u][6] = fmaf(xv[u], w1.z, acc[u][6]);
                acc[u][7] = fmaf(xv[u], w1.w, acc[u][7]);
            }
        }
    }
    __syncthreads();   // everyone done reading Xs -> overwrite with f
    int col = tx * 8;
    #pragma unroll
    for (int u = 0; u < 4; u++) {
        int row = ty * 4 + u;
        int sc = s_kf[row];
        float4 k0 = *(const float4*)&g_kf[sc * DIM + col];
        float4 k1 = *(const float4*)&g_kf[sc * DIM + col + 4];
        Xs[row][col + 0] = tanhf(acc[u][0] + k0.x);
        Xs[row][col + 1] = tanhf(acc[u][1] + k0.y);
        Xs[row][col + 2] = tanhf(acc[u][2] + k0.z);
        Xs[row][col + 3] = tanhf(acc[u][3] + k0.w);
        Xs[row][col + 4] = tanhf(acc[u][4] + k1.x);
        Xs[row][col + 5] = tanhf(acc[u][5] + k1.y);
        Xs[row][col + 6] = tanhf(acc[u][6] + k1.z);
        Xs[row][col + 7] = tanhf(acc[u][7] + k1.w);
    }
    __syncthreads();
    int wid = tid >> 5, lane = tid & 31;
    for (int rr = wid * 8; rr < wid * 8 + 8; rr++) {
        int ns = s_nx[rr];
        int idx = (ns < NUM_C) ? ns : (NUM_C - 1);
        const float* pw = p_W + idx * DIM;
        float a = 0.f;
        #pragma unroll
        for (int q = 0; q < 4; q++) a = fmaf(Xs[rr][lane + 32 * q], pw[lane + 32 * q], a);
        #pragma unroll
        for (int off = 16; off; off >>= 1) a += __shfl_xor_sync(~0u, a, off);
        if (lane == 0) {
            float pr = sigmoidf_(a + p_b[idx]);
            out[row0 + rr] = (ns < NUM_C) ? pr : 0.f;
        }
    }
}

// ---------------- launch: forked-capture stream graph ----------------------
extern "C" void kernel_launch(void* const* d_in, const int* in_sizes, int n_in,
                              void* d_out, int out_size) {
    const int*   skill  = (const int*)d_in[0];
    const int*   answer = (const int*)d_in[1];
    const float* k_emb  = (const float*)d_in[2];
    const float* v_emb  = (const float*)d_in[3];
    const float* Mk     = (const float*)d_in[4];
    const float* Mv0    = (const float*)d_in[5];
    const float* f_W    = (const float*)d_in[6];
    const float* f_b    = (const float*)d_in[7];
    const float* p_W    = (const float*)d_in[8];
    const float* p_b    = (const float*)d_in[9];
    const float* e_W    = (const float*)d_in[10];
    const float* e_b    = (const float*)d_in[11];
    const float* a_W    = (const float*)d_in[12];
    const float* a_b    = (const float*)d_in[13];
    float* out = (float*)d_out;

    static cudaStream_t sA = nullptr, sB = nullptr, sC = nullptr;
    static cudaEvent_t evR = nullptr, evA = nullptr, evB = nullptr, evC = nullptr;
    if (!sA) {   // first call = correctness run (not captured): safe to create
        cudaStreamCreateWithFlags(&sA, cudaStreamNonBlocking);
        cudaStreamCreateWithFlags(&sB, cudaStreamNonBlocking);
        cudaStreamCreateWithFlags(&sC, cudaStreamNonBlocking);
        cudaEventCreateWithFlags(&evR, cudaEventDisableTiming);
        cudaEventCreateWithFlags(&evA, cudaEventDisableTiming);
        cudaEventCreateWithFlags(&evB, cudaEventDisableTiming);
        cudaEventCreateWithFlags(&evC, cudaEventDisableTiming);
    }

    cudaEventRecord(evR, 0);
    cudaStreamWaitEvent(sA, evR, 0);
    cudaStreamWaitEvent(sB, evR, 0);
    cudaStreamWaitEvent(sC, evR, 0);

    k_wtable<<<125, 256, 0, sA>>>(k_emb, Mk);
    k_ea    <<<125, 256, 0, sB>>>(v_emb, e_b, a_b, e_W, a_W);
    k_kfT   <<<71, 256, 0, sC>>>(k_emb, f_b, f_W);      // overlaps scan

    cudaEventRecord(evA, sA);
    cudaEventRecord(evB, sB);
    cudaEventRecord(evC, sC);

    cudaStreamWaitEvent(0, evA, 0);
    cudaStreamWaitEvent(0, evB, 0);
    k_scan<<<512, 128>>>(skill, answer, Mv0);

    cudaStreamWaitEvent(0, evC, 0);
    k_fpred<<<199, 256>>>(skill, p_W, p_b, out);
}